// round 8
// baseline (speedup 1.0000x reference)
#include <cuda_runtime.h>
#include <cuda_bf16.h>
#include <cstdint>

#define D4 32               // float4 per full row (D=128)
#define QPC 8               // float4-quads per CTA (32 cols = 128B contiguous/row)
#define NCB 4               // column blocks per row
#define NQ 4                // row quarters per slot
#define THREADS 512
#define RB (THREADS / QPC)  // 64 row-bases
#define NWARP (THREADS / 32)
#define MAXSLOTS 16384
#define NCTAS 608           // 4 CTAs/SM x 152 SMs, all co-resident

// per slot: NQ quarters x (8 float4 sum + 8 float4 sq) = 64 float4
__device__ float4 g_part[MAXSLOTS * 64];
__device__ int    g_cnt [MAXSLOTS];

__global__ void zero_counters(int nslots) {
    int i = blockIdx.x * blockDim.x + threadIdx.x;
    if (i < nslots) g_cnt[i] = 0;
}

struct Slice {
    int slot, myStart, myCnt;
    float fcnt;
    long colq;
};

__device__ __forceinline__ Slice decode(int s, const int* __restrict__ batch, int quad) {
    Slice sl;
    const int qf = s & (NQ - 1);
    sl.slot = s >> 2;
    const int cb = sl.slot & (NCB - 1);
    const int g  = sl.slot >> 2;
    const int start = batch[g];
    const int cnt   = batch[g + 1] - start;
    const int qlen  = cnt >> 2;
    sl.myStart = start + qf * qlen;
    sl.myCnt   = (qf == NQ - 1) ? (cnt - 3 * qlen) : qlen;
    sl.fcnt    = (float)cnt;
    sl.colq    = (long)cb * QPC + quad;
    return sl;
}

__global__ __launch_bounds__(THREADS, 4)
void graphnorm_persist(const float* __restrict__ x,
                       const float* __restrict__ gamma,
                       const float* __restrict__ beta,
                       const int* __restrict__ batch,
                       float* __restrict__ out,
                       int total_slices)
{
    __shared__ float4 psum[NWARP][QPC];
    __shared__ float4 psq [NWARP][QPC];
    __shared__ float4 smean[QPC], sinv[QPC];

    const int quad = threadIdx.x & (QPC - 1);
    const int rb   = threadIdx.x >> 3;
    const int warp = threadIdx.x >> 5;
    const int lane = threadIdx.x & 31;

    const float4* __restrict__ xv = (const float4*)x;
    float4* __restrict__ ov = (float4*)out;

    int prev = -1;

    for (int s = blockIdx.x; s < total_slices; s += NCTAS) {
        // ================= pass 1: accumulate + publish slice s ============
        {
            Slice sl = decode(s, batch, quad);
            float4 a = make_float4(0.f, 0.f, 0.f, 0.f);
            float4 q = make_float4(0.f, 0.f, 0.f, 0.f);
            for (int r = rb; r < sl.myCnt; r += RB) {
                float4 v = xv[(long)(sl.myStart + r) * D4 + sl.colq];
                a.x += v.x; a.y += v.y; a.z += v.z; a.w += v.w;
                q.x += v.x * v.x; q.y += v.y * v.y; q.z += v.z * v.z; q.w += v.w * v.w;
            }
            #pragma unroll
            for (int off = 8; off <= 16; off <<= 1) {
                a.x += __shfl_xor_sync(0xffffffffu, a.x, off);
                a.y += __shfl_xor_sync(0xffffffffu, a.y, off);
                a.z += __shfl_xor_sync(0xffffffffu, a.z, off);
                a.w += __shfl_xor_sync(0xffffffffu, a.w, off);
                q.x += __shfl_xor_sync(0xffffffffu, q.x, off);
                q.y += __shfl_xor_sync(0xffffffffu, q.y, off);
                q.z += __shfl_xor_sync(0xffffffffu, q.z, off);
                q.w += __shfl_xor_sync(0xffffffffu, q.w, off);
            }
            if (lane < QPC) { psum[warp][quad] = a; psq[warp][quad] = q; }
            __syncthreads();
            if (threadIdx.x < QPC) {
                float4 ts = make_float4(0.f, 0.f, 0.f, 0.f);
                float4 tq = make_float4(0.f, 0.f, 0.f, 0.f);
                #pragma unroll
                for (int w = 0; w < NWARP; w++) {
                    float4 u = psum[w][threadIdx.x];
                    float4 v = psq [w][threadIdx.x];
                    ts.x += u.x; ts.y += u.y; ts.z += u.z; ts.w += u.w;
                    tq.x += v.x; tq.y += v.y; tq.z += v.z; tq.w += v.w;
                }
                float4* base = &g_part[(long)sl.slot * 64 + (s & 3) * 16];
                base[threadIdx.x]     = ts;
                base[threadIdx.x + 8] = tq;
            }
            __syncthreads();    // partial stores happen-before the release-arrive
            if (threadIdx.x == 0) {
                asm volatile("red.add.release.gpu.global.s32 [%0], 1;"
                             :: "l"(&g_cnt[sl.slot]) : "memory");
            }
        }

        // ================= pass 2: finish slice prev (partners long done) ===
        if (prev >= 0) {
            Slice sl = decode(prev, batch, quad);
            if (threadIdx.x == 0) {
                int v;
                do {
                    asm volatile("ld.acquire.gpu.global.s32 %0, [%1];"
                                 : "=r"(v) : "l"(&g_cnt[sl.slot]) : "memory");
                } while (v < NQ);
            }
            __syncthreads();
            if (threadIdx.x < QPC) {
                const float4* base = &g_part[(long)sl.slot * 64];
                float4 ts = make_float4(0.f, 0.f, 0.f, 0.f);
                float4 tq = make_float4(0.f, 0.f, 0.f, 0.f);
                #pragma unroll
                for (int qf = 0; qf < NQ; qf++) {
                    float4 u = __ldcg(&base[qf * 16 + threadIdx.x]);
                    float4 v = __ldcg(&base[qf * 16 + threadIdx.x + 8]);
                    ts.x += u.x; ts.y += u.y; ts.z += u.z; ts.w += u.w;
                    tq.x += v.x; tq.y += v.y; tq.z += v.z; tq.w += v.w;
                }
                float4 m, iv;
                m.x = ts.x / sl.fcnt; m.y = ts.y / sl.fcnt;
                m.z = ts.z / sl.fcnt; m.w = ts.w / sl.fcnt;
                float denom = sl.fcnt - 1.0f;
                iv.x = 1.0f / (sqrtf(fmaxf((tq.x - sl.fcnt * m.x * m.x) / denom, 0.f)) + 1e-5f);
                iv.y = 1.0f / (sqrtf(fmaxf((tq.y - sl.fcnt * m.y * m.y) / denom, 0.f)) + 1e-5f);
                iv.z = 1.0f / (sqrtf(fmaxf((tq.z - sl.fcnt * m.z * m.z) / denom, 0.f)) + 1e-5f);
                iv.w = 1.0f / (sqrtf(fmaxf((tq.w - sl.fcnt * m.w * m.w) / denom, 0.f)) + 1e-5f);
                smean[threadIdx.x] = m;
                sinv [threadIdx.x] = iv;
            }
            __syncthreads();

            const float4 g4 = ((const float4*)gamma)[sl.colq];
            const float4 b4 = ((const float4*)beta)[sl.colq];
            const float4 m  = smean[quad];
            const float4 iv = sinv [quad];
            for (int r = rb; r < sl.myCnt; r += RB) {
                const long idx = (long)(sl.myStart + r) * D4 + sl.colq;
                float4 v = __ldcs(&xv[idx]);          // L2-resident re-read
                float4 o;
                o.x = g4.x * (v.x - m.x) * iv.x + b4.x;
                o.y = g4.y * (v.y - m.y) * iv.y + b4.y;
                o.z = g4.z * (v.z - m.z) * iv.z + b4.z;
                o.w = g4.w * (v.w - m.w) * iv.w + b4.w;
                __stcs(&ov[idx], o);                  // streaming store
            }
            __syncthreads();   // smean/sinv reuse safety for next iteration
        }
        prev = s;
    }

    // ================= epilogue: finish last slice ======================
    if (prev >= 0) {
        Slice sl = decode(prev, batch, quad);
        if (threadIdx.x == 0) {
            int v;
            do {
                asm volatile("ld.acquire.gpu.global.s32 %0, [%1];"
                             : "=r"(v) : "l"(&g_cnt[sl.slot]) : "memory");
            } while (v < NQ);
        }
        __syncthreads();
        if (threadIdx.x < QPC) {
            const float4* base = &g_part[(long)sl.slot * 64];
            float4 ts = make_float4(0.f, 0.f, 0.f, 0.f);
            float4 tq = make_float4(0.f, 0.f, 0.f, 0.f);
            #pragma unroll
            for (int qf = 0; qf < NQ; qf++) {
                float4 u = __ldcg(&base[qf * 16 + threadIdx.x]);
                float4 v = __ldcg(&base[qf * 16 + threadIdx.x + 8]);
                ts.x += u.x; ts.y += u.y; ts.z += u.z; ts.w += u.w;
                tq.x += v.x; tq.y += v.y; tq.z += v.z; tq.w += v.w;
            }
            float4 m, iv;
            m.x = ts.x / sl.fcnt; m.y = ts.y / sl.fcnt;
            m.z = ts.z / sl.fcnt; m.w = ts.w / sl.fcnt;
            float denom = sl.fcnt - 1.0f;
            iv.x = 1.0f / (sqrtf(fmaxf((tq.x - sl.fcnt * m.x * m.x) / denom, 0.f)) + 1e-5f);
            iv.y = 1.0f / (sqrtf(fmaxf((tq.y - sl.fcnt * m.y * m.y) / denom, 0.f)) + 1e-5f);
            iv.z = 1.0f / (sqrtf(fmaxf((tq.z - sl.fcnt * m.z * m.z) / denom, 0.f)) + 1e-5f);
            iv.w = 1.0f / (sqrtf(fmaxf((tq.w - sl.fcnt * m.w * m.w) / denom, 0.f)) + 1e-5f);
            smean[threadIdx.x] = m;
            sinv [threadIdx.x] = iv;
        }
        __syncthreads();

        const float4 g4 = ((const float4*)gamma)[sl.colq];
        const float4 b4 = ((const float4*)beta)[sl.colq];
        const float4 m  = smean[quad];
        const float4 iv = sinv [quad];
        for (int r = rb; r < sl.myCnt; r += RB) {
            const long idx = (long)(sl.myStart + r) * D4 + sl.colq;
            float4 v = __ldcs(&xv[idx]);
            float4 o;
            o.x = g4.x * (v.x - m.x) * iv.x + b4.x;
            o.y = g4.y * (v.y - m.y) * iv.y + b4.y;
            o.z = g4.z * (v.z - m.z) * iv.z + b4.z;
            o.w = g4.w * (v.w - m.w) * iv.w + b4.w;
            __stcs(&ov[idx], o);
        }
    }
}

extern "C" void kernel_launch(void* const* d_in, const int* in_sizes, int n_in,
                              void* d_out, int out_size)
{
    const float* x     = (const float*)d_in[0];
    const float* gamma = (const float*)d_in[1];
    const float* beta  = (const float*)d_in[2];
    const int*   batch = (const int*)d_in[3];
    float* out = (float*)d_out;

    const int G = in_sizes[3] - 1;
    const int nslots = G * NCB;
    const int total_slices = nslots * NQ;

    zero_counters<<<(nslots + 255) / 256, 256>>>(nslots);
    graphnorm_persist<<<NCTAS, THREADS>>>(x, gamma, beta, batch, out, total_slices);
}

// round 10
// speedup vs baseline: 1.0666x; 1.0666x over previous
#include <cuda_runtime.h>
#include <cuda_bf16.h>
#include <cstdint>

#define D4 32               // float4 per full row (D=128)
#define QPC 8               // float4-quads per CTA (32 cols = 128B contiguous/row)
#define THREADS 512
#define RB2 (THREADS / QPC) // 64 row-bases for pass 2
#define RB1 (THREADS / 4)   // 128 row-bases for pass 1 (32B/thread)
#define NWARP (THREADS / 32)

// pass-1 load: 256-bit evict-last (required width for L2::evict_last on sm_103a)
__device__ __forceinline__ void ld_evict_last8(const float* p, float4& a, float4& b) {
    uint32_t r0, r1, r2, r3, r4, r5, r6, r7;
    asm("ld.global.L2::evict_last.v8.b32 {%0,%1,%2,%3,%4,%5,%6,%7}, [%8];"
        : "=r"(r0), "=r"(r1), "=r"(r2), "=r"(r3),
          "=r"(r4), "=r"(r5), "=r"(r6), "=r"(r7) : "l"(p));
    a.x = __uint_as_float(r0); a.y = __uint_as_float(r1);
    a.z = __uint_as_float(r2); a.w = __uint_as_float(r3);
    b.x = __uint_as_float(r4); b.y = __uint_as_float(r5);
    b.z = __uint_as_float(r6); b.w = __uint_as_float(r7);
}

__global__ __launch_bounds__(THREADS, 4)
void graphnorm_l2pin(const float* __restrict__ x,
                     const float* __restrict__ gamma,
                     const float* __restrict__ beta,
                     const int* __restrict__ batch,
                     float* __restrict__ out)
{
    __shared__ float4 psum[NWARP][QPC];
    __shared__ float4 psq [NWARP][QPC];
    __shared__ float4 smean[QPC], sinv[QPC];

    const int cb   = blockIdx.x;                  // column block 0..3 (fastest)
    const int g    = blockIdx.y;                  // graph
    const int warp = threadIdx.x >> 5;
    const int lane = threadIdx.x & 31;

    const int start = batch[g];
    const int end   = batch[g + 1];
    const int cnt   = end - start;
    const float fcnt = (float)cnt;

    const float* __restrict__ xs = x;
    const float4* __restrict__ xv = (const float4*)x;
    float4* __restrict__ ov = (float4*)out;

    // ---- pass 1: 32B/thread evict-last reads, accumulate sum / sumsq ----
    const int oct = threadIdx.x & 3;              // 32B chunk within 128B row
    const int rb1 = threadIdx.x >> 2;             // 0..127
    const long coloct = (long)cb * 32 + oct * 8;  // float col of this 32B chunk

    float4 sa = make_float4(0.f, 0.f, 0.f, 0.f);
    float4 sb = make_float4(0.f, 0.f, 0.f, 0.f);
    float4 qa = make_float4(0.f, 0.f, 0.f, 0.f);
    float4 qb = make_float4(0.f, 0.f, 0.f, 0.f);
    for (int r = rb1; r < cnt; r += RB1) {
        float4 va, vb;
        ld_evict_last8(&xs[(long)(start + r) * 128 + coloct], va, vb);
        sa.x += va.x; sa.y += va.y; sa.z += va.z; sa.w += va.w;
        qa.x += va.x * va.x; qa.y += va.y * va.y; qa.z += va.z * va.z; qa.w += va.w * va.w;
        sb.x += vb.x; sb.y += vb.y; sb.z += vb.z; sb.w += vb.w;
        qb.x += vb.x * vb.x; qb.y += vb.y * vb.y; qb.z += vb.z * vb.z; qb.w += vb.w * vb.w;
    }

    // ---- warp reduce: lanes {oct, oct+4, ..., oct+28} share a 32B chunk ----
    #pragma unroll
    for (int off = 4; off <= 16; off <<= 1) {
        sa.x += __shfl_xor_sync(0xffffffffu, sa.x, off);
        sa.y += __shfl_xor_sync(0xffffffffu, sa.y, off);
        sa.z += __shfl_xor_sync(0xffffffffu, sa.z, off);
        sa.w += __shfl_xor_sync(0xffffffffu, sa.w, off);
        sb.x += __shfl_xor_sync(0xffffffffu, sb.x, off);
        sb.y += __shfl_xor_sync(0xffffffffu, sb.y, off);
        sb.z += __shfl_xor_sync(0xffffffffu, sb.z, off);
        sb.w += __shfl_xor_sync(0xffffffffu, sb.w, off);
        qa.x += __shfl_xor_sync(0xffffffffu, qa.x, off);
        qa.y += __shfl_xor_sync(0xffffffffu, qa.y, off);
        qa.z += __shfl_xor_sync(0xffffffffu, qa.z, off);
        qa.w += __shfl_xor_sync(0xffffffffu, qa.w, off);
        qb.x += __shfl_xor_sync(0xffffffffu, qb.x, off);
        qb.y += __shfl_xor_sync(0xffffffffu, qb.y, off);
        qb.z += __shfl_xor_sync(0xffffffffu, qb.z, off);
        qb.w += __shfl_xor_sync(0xffffffffu, qb.w, off);
    }
    // lane oct (0..3) holds chunk totals: two float4 quads (2*oct, 2*oct+1)
    if (lane < 4) {
        psum[warp][2 * lane]     = sa;
        psum[warp][2 * lane + 1] = sb;
        psq [warp][2 * lane]     = qa;
        psq [warp][2 * lane + 1] = qb;
    }
    __syncthreads();

    // ---- final reduce across warps + stats (QPC threads, one per quad) ----
    if (threadIdx.x < QPC) {
        float4 ts = make_float4(0.f, 0.f, 0.f, 0.f);
        float4 tq = make_float4(0.f, 0.f, 0.f, 0.f);
        #pragma unroll
        for (int w = 0; w < NWARP; w++) {
            float4 a = psum[w][threadIdx.x];
            float4 b = psq [w][threadIdx.x];
            ts.x += a.x; ts.y += a.y; ts.z += a.z; ts.w += a.w;
            tq.x += b.x; tq.y += b.y; tq.z += b.z; tq.w += b.w;
        }
        float4 m, iv;
        m.x = ts.x / fcnt; m.y = ts.y / fcnt; m.z = ts.z / fcnt; m.w = ts.w / fcnt;
        float denom = fcnt - 1.0f;
        iv.x = 1.0f / (sqrtf(fmaxf((tq.x - fcnt * m.x * m.x) / denom, 0.f)) + 1e-5f);
        iv.y = 1.0f / (sqrtf(fmaxf((tq.y - fcnt * m.y * m.y) / denom, 0.f)) + 1e-5f);
        iv.z = 1.0f / (sqrtf(fmaxf((tq.z - fcnt * m.z * m.z) / denom, 0.f)) + 1e-5f);
        iv.w = 1.0f / (sqrtf(fmaxf((tq.w - fcnt * m.w * m.w) / denom, 0.f)) + 1e-5f);
        smean[threadIdx.x] = m;
        sinv [threadIdx.x] = iv;
    }
    __syncthreads();

    // ---- pass 2: re-read (L2 hit, evict-first), streaming store ----
    const int quad = threadIdx.x & (QPC - 1);     // 0..7
    const int rb2  = threadIdx.x >> 3;            // 0..63
    const long colq = (long)cb * QPC + quad;      // float4 col 0..31

    const float4 g4 = ((const float4*)gamma)[colq];
    const float4 b4 = ((const float4*)beta)[colq];
    const float4 m  = smean[quad];
    const float4 iv = sinv [quad];

    for (int r = rb2; r < cnt; r += RB2) {
        const long idx = (long)(start + r) * D4 + colq;
        float4 v = __ldcs(&xv[idx]);          // evict-first: dead after this read
        float4 o;
        o.x = g4.x * (v.x - m.x) * iv.x + b4.x;
        o.y = g4.y * (v.y - m.y) * iv.y + b4.y;
        o.z = g4.z * (v.z - m.z) * iv.z + b4.z;
        o.w = g4.w * (v.w - m.w) * iv.w + b4.w;
        __stcs(&ov[idx], o);                  // streaming store, no L2 pollution
    }
}

extern "C" void kernel_launch(void* const* d_in, const int* in_sizes, int n_in,
                              void* d_out, int out_size)
{
    const float* x     = (const float*)d_in[0];
    const float* gamma = (const float*)d_in[1];
    const float* beta  = (const float*)d_in[2];
    const int*   batch = (const int*)d_in[3];
    float* out = (float*)d_out;

    const int G = in_sizes[3] - 1;
    dim3 grid(D4 / QPC, G);   // (column-block fastest, graph)
    graphnorm_l2pin<<<grid, THREADS>>>(x, gamma, beta, batch, out);
}